// round 13
// baseline (speedup 1.0000x reference)
#include <cuda_runtime.h>
#include <math.h>

#define N_NODES 50000
#define N_EDGES 800000
#define D_IN    64
#define D_HID   256
#define BN_EPS  1e-5f
#define N_CHUNKS ((N_NODES + 1023) / 1024)   // 49

#define NBG     32    // nodes per block in big GEMM kernels (2 groups x 16)
#define GRID_G  ((N_NODES + NBG - 1) / NBG)  // 1563 (tail block has 16 nodes)

// smem layouts (floats). group-1 node regions offset by +8 floats (32B) to
// decorrelate LDS banks between the two groups' broadcast reads.
#define SZ_GRP   (16 * D_HID + 8)            // 4104
#define SX_GRP   (16 * D_IN + 8)             // 1032
#define GATE_SZ  (2 * SZ_GRP)                // 8208
#define GATE_SX  (2 * SX_GRP)                // 2064
#define WBUF_F   (64 * D_HID)                // 16384 floats = 64 KB
#define GATE_SMEM_F (GATE_SZ + GATE_SX + WBUF_F)       // 26656 floats
#define GCN_SMEM_F  (2 * SX_GRP + WBUF_F)              // 18448 floats

// ---------------- scratch (no allocs allowed) ----------------
__device__ float g_dinv[N_NODES];
__device__ __align__(16) float g_xp[(size_t)N_NODES * D_IN];   // xs * dinv[row]
__device__ __align__(16) float g_y[(size_t)N_NODES * D_IN];    // aggregated inputs
__device__ __align__(16) float g_z[(size_t)N_NODES * D_HID];   // tanh(y @ W_gcn + b)
__device__ float g_sum[D_HID];
__device__ float g_sumsq[D_HID];
// CSR scratch
__device__ int g_deg[N_NODES];
__device__ int g_rowptr[N_NODES + 1];
__device__ int g_cursor[N_NODES];
__device__ int g_csrc[N_EDGES];
__device__ int g_btot[N_CHUNKS];
__device__ int g_boff[N_CHUNKS];

// ---------------- packed f32x2 helpers (FFMA2 on sm_103a) ----------------
__device__ __forceinline__ unsigned long long pk2(float lo, float hi) {
    unsigned long long r;
    asm("mov.b64 %0, {%1, %2};" : "=l"(r) : "f"(lo), "f"(hi));
    return r;
}
__device__ __forceinline__ float2 upk2(unsigned long long v) {
    float2 f;
    asm("mov.b64 {%0, %1}, %2;" : "=f"(f.x), "=f"(f.y) : "l"(v));
    return f;
}
__device__ __forceinline__ void fma2(unsigned long long& d, unsigned long long a,
                                     unsigned long long b) {
    asm("fma.rn.f32x2 %0, %1, %2, %0;" : "+l"(d) : "l"(a), "l"(b));
}

// ---------------- K0: zero degree + BN stats ----------------
__global__ void k_init() {
    int i = blockIdx.x * blockDim.x + threadIdx.x;
    if (i < N_NODES) g_deg[i] = 0;
    if (i < D_HID) { g_sum[i] = 0.0f; g_sumsq[i] = 0.0f; }
}

// ---------------- K1: degree histogram over dst ----------------
__global__ void k_degree(const int* __restrict__ ei) {
    int e = blockIdx.x * blockDim.x + threadIdx.x;
    if (e < N_EDGES) atomicAdd(&g_deg[ei[N_EDGES + e]], 1);
}

// ---------------- K2a: per-1024-chunk exclusive scan + chunk totals ----------------
__global__ void __launch_bounds__(1024) k_scan1() {
    __shared__ int warpsums[32];
    int t = threadIdx.x, lane = t & 31, w = t >> 5;
    int i = blockIdx.x * 1024 + t;
    int v = (i < N_NODES) ? g_deg[i] : 0;
    int x = v;
#pragma unroll
    for (int off = 1; off < 32; off <<= 1) {
        int y = __shfl_up_sync(0xffffffffu, x, off);
        if (lane >= off) x += y;
    }
    if (lane == 31) warpsums[w] = x;
    __syncthreads();
    if (w == 0) {
        int s = warpsums[lane];
#pragma unroll
        for (int off = 1; off < 32; off <<= 1) {
            int y = __shfl_up_sync(0xffffffffu, s, off);
            if (lane >= off) s += y;
        }
        warpsums[lane] = s;
    }
    __syncthreads();
    int excl = ((w > 0) ? warpsums[w - 1] : 0) + x - v;
    if (i < N_NODES) g_rowptr[i] = excl;
    if (t == 0) g_btot[blockIdx.x] = warpsums[31];
}

// ---------------- K2b: scan chunk totals (1 block) ----------------
__global__ void k_scan2() {
    __shared__ int w0tot;
    int t = threadIdx.x, lane = t & 31, w = t >> 5;
    int v = (t < N_CHUNKS) ? g_btot[t] : 0;
    int x = v;
#pragma unroll
    for (int off = 1; off < 32; off <<= 1) {
        int y = __shfl_up_sync(0xffffffffu, x, off);
        if (lane >= off) x += y;
    }
    if (w == 0 && lane == 31) w0tot = x;
    __syncthreads();
    int excl = x - v + (w ? w0tot : 0);
    if (t < N_CHUNKS) g_boff[t] = excl;
    if (t == N_CHUNKS - 1) g_rowptr[N_NODES] = excl + v;
}

// ---------------- K2c: apply chunk offsets; cursor; dinv ----------------
__global__ void k_scan3() {
    int i = blockIdx.x * blockDim.x + threadIdx.x;
    if (i < N_NODES) {
        int rp = g_rowptr[i] + g_boff[i >> 10];
        g_rowptr[i] = rp;
        g_cursor[i] = rp;
        g_dinv[i] = rsqrtf((float)(g_deg[i] + 1));   // +1 self loop
    }
}

// ---------------- K3: CSR fill ----------------
__global__ void k_fill(const int* __restrict__ ei) {
    int e = blockIdx.x * blockDim.x + threadIdx.x;
    if (e < N_EDGES) {
        int s = ei[e];
        int d = ei[N_EDGES + e];
        int pos = atomicAdd(&g_cursor[d], 1);
        g_csrc[pos] = s;
    }
}

// ---------------- K3b: xs' = xs * dinv[row] ----------------
__global__ void k_xscale(const float* __restrict__ xs) {
    int i = blockIdx.x * blockDim.x + threadIdx.x;   // float4 index
    if (i < N_NODES * D_IN / 4) {
        float di = g_dinv[i >> 4];
        float4 v = ((const float4*)xs)[i];
        v.x *= di; v.y *= di; v.z *= di; v.w *= di;
        ((float4*)g_xp)[i] = v;
    }
}

// ---------------- K4: CSR gather in D_IN space ----------------
__global__ void __launch_bounds__(256) k_gather_x() {
    int t = threadIdx.x;
    int n = blockIdx.x * 16 + (t >> 4);
    int c = t & 15;
    int g0 = t & ~15;
    const float4* X = (const float4*)g_xp;

    int r_s = 0, e_s = 0;
    float di_s = 0.0f;
    if (c == 0) {
        r_s = g_rowptr[n];
        e_s = g_rowptr[n + 1];
        di_s = g_dinv[n];
    }
    int r  = __shfl_sync(0xffffffffu, r_s, g0 & 31);
    int e  = __shfl_sync(0xffffffffu, e_s, g0 & 31);
    float di = __shfl_sync(0xffffffffu, di_s, g0 & 31);

    float4 acc = X[(size_t)n * 16 + c];   // self-loop term
    for (; r + 4 <= e; r += 4) {
        int i0 = __ldg(&g_csrc[r]);
        int i1 = __ldg(&g_csrc[r + 1]);
        int i2 = __ldg(&g_csrc[r + 2]);
        int i3 = __ldg(&g_csrc[r + 3]);
        float4 a0 = X[(size_t)i0 * 16 + c];
        float4 a1 = X[(size_t)i1 * 16 + c];
        float4 a2 = X[(size_t)i2 * 16 + c];
        float4 a3 = X[(size_t)i3 * 16 + c];
        acc.x += (a0.x + a1.x) + (a2.x + a3.x);
        acc.y += (a0.y + a1.y) + (a2.y + a3.y);
        acc.z += (a0.z + a1.z) + (a2.z + a3.z);
        acc.w += (a0.w + a1.w) + (a2.w + a3.w);
    }
    for (; r < e; r++) {
        float4 a0 = X[(size_t)__ldg(&g_csrc[r]) * 16 + c];
        acc.x += a0.x; acc.y += a0.y; acc.z += a0.z; acc.w += a0.w;
    }
    acc.x *= di; acc.y *= di; acc.z *= di; acc.w *= di;
    ((float4*)g_y)[(size_t)n * 16 + c] = acc;
}

// ---------------- K5: z = tanh(y @ W_gcn + b_gcn)  (NB=32, smem-staged weights) ----------------
__global__ void __launch_bounds__(512, 1) k_gcn_gemm(const float* __restrict__ Wg,
                                                     const float* __restrict__ b_gcn) {
    extern __shared__ __align__(16) float dsm[];
    float* sy   = dsm;                 // 2 * SX_GRP
    float* wbuf = dsm + 2 * SX_GRP;    // WBUF_F

    int n0  = blockIdx.x * NBG;
    int t   = threadIdx.x;
    int j   = t & 255;
    int grp = t >> 8;
    float* syg = sy + grp * SX_GRP;

    // each group loads its 16 nodes of g_y (1024 floats, 4/thread), zero OOB
#pragma unroll
    for (int rI = 0; rI < 4; rI++) {
        int idx = j + 256 * rI;                 // 0..1023 within group region
        int node = n0 + grp * 16 + (idx >> 6);
        syg[idx] = (node < N_NODES) ? g_y[(size_t)node * D_IN + (idx & 63)] : 0.0f;
    }
    // stage Wg (64x256) cooperatively, float4 coalesced
#pragma unroll
    for (int i = 0; i < 8; i++)
        ((float4*)wbuf)[t + 512 * i] = ((const float4*)Wg)[t + 512 * i];
    __syncthreads();

    unsigned long long acc2[16];
#pragma unroll
    for (int nb = 0; nb < 16; nb++) acc2[nb] = 0ULL;

#pragma unroll
    for (int k4 = 0; k4 < 16; k4++) {
        float w0 = wbuf[(4 * k4 + 0) * D_HID + j];
        float w1 = wbuf[(4 * k4 + 1) * D_HID + j];
        float w2 = wbuf[(4 * k4 + 2) * D_HID + j];
        float w3 = wbuf[(4 * k4 + 3) * D_HID + j];
        unsigned long long wp0 = pk2(w0, w1), wp1 = pk2(w2, w3);
#pragma unroll
        for (int nb = 0; nb < 16; nb++) {
            ulonglong2 yy = ((const ulonglong2*)(syg + nb * D_IN))[k4];
            fma2(acc2[nb], yy.x, wp0);
            fma2(acc2[nb], yy.y, wp1);
        }
    }

    float b = b_gcn[j];
#pragma unroll
    for (int nb = 0; nb < 16; nb++) {
        int node = n0 + grp * 16 + nb;
        if (node < N_NODES) {
            float2 f = upk2(acc2[nb]);
            g_z[(size_t)node * D_HID + j] = tanhf(f.x + f.y + b);
        }
    }
}

// ---------------- K6: gate+lin GEMM + residual + relu + BN stats (NB=32, smem weights) ----------------
__global__ void __launch_bounds__(512, 1) k_gate(const float* __restrict__ xs,
                                                 const float* __restrict__ Wgate,
                                                 const float* __restrict__ b_gate,
                                                 const float* __restrict__ Wlin,
                                                 const float* __restrict__ b_lin,
                                                 float* __restrict__ out) {
    extern __shared__ __align__(16) float dsm[];
    float* sz   = dsm;                            // GATE_SZ
    float* sx   = dsm + GATE_SZ;                  // GATE_SX
    float* wbuf = dsm + GATE_SZ + GATE_SX;        // WBUF_F

    int n0  = blockIdx.x * NBG;
    int t   = threadIdx.x;
    int j   = t & 255;
    int grp = t >> 8;
    float* szg = sz + grp * SZ_GRP;
    float* sxg = sx + grp * SX_GRP;

    // load 16 z rows per group (4096 floats, 16/thread), zero OOB
#pragma unroll
    for (int rI = 0; rI < 16; rI++) {
        int idx = j + 256 * rI;
        int node = n0 + grp * 16 + (idx >> 8);
        szg[idx] = (node < N_NODES) ? g_z[(size_t)node * D_HID + (idx & 255)] : 0.0f;
    }
    // load 16 xs rows per group (1024 floats, 4/thread)
#pragma unroll
    for (int rI = 0; rI < 4; rI++) {
        int idx = j + 256 * rI;
        int node = n0 + grp * 16 + (idx >> 6);
        sxg[idx] = (node < N_NODES) ? xs[(size_t)node * D_IN + (idx & 63)] : 0.0f;
    }

    unsigned long long accg2[16];
#pragma unroll
    for (int nb = 0; nb < 16; nb++) accg2[nb] = 0ULL;

    // gate GEMM: K=256 in four 64-row weight tiles staged through smem
    for (int kt = 0; kt < 4; kt++) {
        __syncthreads();   // prev tile consumed (or initial loads done)
#pragma unroll
        for (int i = 0; i < 8; i++)
            ((float4*)wbuf)[t + 512 * i] =
                ((const float4*)(Wgate + kt * 64 * D_HID))[t + 512 * i];
        __syncthreads();
#pragma unroll
        for (int k4 = 0; k4 < 16; k4++) {
            float w0 = wbuf[(4 * k4 + 0) * D_HID + j];
            float w1 = wbuf[(4 * k4 + 1) * D_HID + j];
            float w2 = wbuf[(4 * k4 + 2) * D_HID + j];
            float w3 = wbuf[(4 * k4 + 3) * D_HID + j];
            unsigned long long wp0 = pk2(w0, w1), wp1 = pk2(w2, w3);
            int q = kt * 16 + k4;
#pragma unroll
            for (int nb = 0; nb < 16; nb++) {
                ulonglong2 zz = ((const ulonglong2*)(szg + nb * D_HID))[q];
                fma2(accg2[nb], zz.x, wp0);
                fma2(accg2[nb], zz.y, wp1);
            }
        }
    }
    // collapse gate accumulators (free registers)
    float ag[16];
#pragma unroll
    for (int nb = 0; nb < 16; nb++) {
        float2 fg = upk2(accg2[nb]);
        ag[nb] = fg.x + fg.y;
    }

    // lin GEMM: K=64, one weight tile
    __syncthreads();
#pragma unroll
    for (int i = 0; i < 8; i++)
        ((float4*)wbuf)[t + 512 * i] = ((const float4*)Wlin)[t + 512 * i];
    __syncthreads();

    unsigned long long accl2[16];
#pragma unroll
    for (int nb = 0; nb < 16; nb++) accl2[nb] = 0ULL;
#pragma unroll
    for (int k4 = 0; k4 < 16; k4++) {
        float w0 = wbuf[(4 * k4 + 0) * D_HID + j];
        float w1 = wbuf[(4 * k4 + 1) * D_HID + j];
        float w2 = wbuf[(4 * k4 + 2) * D_HID + j];
        float w3 = wbuf[(4 * k4 + 3) * D_HID + j];
        unsigned long long wp0 = pk2(w0, w1), wp1 = pk2(w2, w3);
#pragma unroll
        for (int nb = 0; nb < 16; nb++) {
            ulonglong2 xx = ((const ulonglong2*)(sxg + nb * D_IN))[k4];
            fma2(accl2[nb], xx.x, wp0);
            fma2(accl2[nb], xx.y, wp1);
        }
    }

    float bg = b_gate[j], bl = b_lin[j];
    float s_loc = 0.0f, q_loc = 0.0f;
#pragma unroll
    for (int nb = 0; nb < 16; nb++) {
        int node = n0 + grp * 16 + nb;
        if (node < N_NODES) {
            float2 fl = upk2(accl2[nb]);
            float al = fl.x + fl.y + bl;
            float g  = 1.0f / (1.0f + expf(-(ag[nb] + bg)));
            float z  = szg[nb * D_HID + j];
            float o  = fmaxf((1.0f - g) * al + g * z, 0.0f);
            out[(size_t)node * D_HID + j] = o;
            s_loc += o;
            q_loc += o * o;
        }
    }
    atomicAdd(&g_sum[j], s_loc);
    atomicAdd(&g_sumsq[j], q_loc);
}

// ---------------- K7: BN normalize in place (float4) ----------------
__global__ void k_bn(float* __restrict__ out,
                     const float* __restrict__ gamma,
                     const float* __restrict__ beta) {
    int i = blockIdx.x * blockDim.x + threadIdx.x;
    if (i < N_NODES * D_HID / 4) {
        int c4 = i & 63;
        const float invN = 1.0f / (float)N_NODES;
        float4 s  = ((const float4*)g_sum)[c4];
        float4 q  = ((const float4*)g_sumsq)[c4];
        float4 gm = ((const float4*)gamma)[c4];
        float4 bt = ((const float4*)beta)[c4];
        float4 v  = ((float4*)out)[i];
        float mu, var;
        mu = s.x * invN; var = q.x * invN - mu * mu;
        v.x = (v.x - mu) * rsqrtf(var + BN_EPS) * gm.x + bt.x;
        mu = s.y * invN; var = q.y * invN - mu * mu;
        v.y = (v.y - mu) * rsqrtf(var + BN_EPS) * gm.y + bt.y;
        mu = s.z * invN; var = q.z * invN - mu * mu;
        v.z = (v.z - mu) * rsqrtf(var + BN_EPS) * gm.z + bt.z;
        mu = s.w * invN; var = q.w * invN - mu * mu;
        v.w = (v.w - mu) * rsqrtf(var + BN_EPS) * gm.w + bt.w;
        ((float4*)out)[i] = v;
    }
}

// ---------------- launch ----------------
extern "C" void kernel_launch(void* const* d_in, const int* in_sizes, int n_in,
                              void* d_out, int out_size) {
    const float* xs     = (const float*)d_in[0];
    const int*   ei     = (const int*)d_in[1];   // int32 (JAX x64-disabled)
    const float* W_gcn  = (const float*)d_in[2];
    const float* b_gcn  = (const float*)d_in[3];
    const float* W_lin  = (const float*)d_in[4];
    const float* b_lin  = (const float*)d_in[5];
    const float* W_gate = (const float*)d_in[6];
    const float* b_gate = (const float*)d_in[7];
    const float* gamma  = (const float*)d_in[8];
    const float* beta   = (const float*)d_in[9];
    float* out = (float*)d_out;

    // opt-in to >48KB dynamic smem (host-side attribute set; capture-safe, idempotent)
    cudaFuncSetAttribute(k_gcn_gemm, cudaFuncAttributeMaxDynamicSharedMemorySize,
                         GCN_SMEM_F * (int)sizeof(float));
    cudaFuncSetAttribute(k_gate, cudaFuncAttributeMaxDynamicSharedMemorySize,
                         GATE_SMEM_F * (int)sizeof(float));

    k_init<<<(N_NODES + 255) / 256, 256>>>();
    k_degree<<<(N_EDGES + 255) / 256, 256>>>(ei);
    k_scan1<<<N_CHUNKS, 1024>>>();
    k_scan2<<<1, 64>>>();
    k_scan3<<<(N_NODES + 255) / 256, 256>>>();
    k_fill<<<(N_EDGES + 255) / 256, 256>>>(ei);
    k_xscale<<<(N_NODES * D_IN / 4 + 255) / 256, 256>>>(xs);
    k_gather_x<<<N_NODES / 16, 256>>>();
    k_gcn_gemm<<<GRID_G, 512, GCN_SMEM_F * sizeof(float)>>>(W_gcn, b_gcn);
    k_gate<<<GRID_G, 512, GATE_SMEM_F * sizeof(float)>>>(xs, W_gate, b_gate,
                                                         W_lin, b_lin, out);
    k_bn<<<(N_NODES * D_HID / 4 + 255) / 256, 256>>>(out, gamma, beta);
}

// round 16
// speedup vs baseline: 1.9011x; 1.9011x over previous
#include <cuda_runtime.h>
#include <cuda_bf16.h>
#include <math.h>
#include <stdint.h>

#define N_NODES 50000
#define N_EDGES 800000
#define D_IN    64
#define D_HID   256
#define BN_EPS  1e-5f
#define N_CHUNKS ((N_NODES + 1023) / 1024)   // 49
#define N_MT     ((N_NODES + 127) / 128)     // 391 m-tiles

// smem tile geometry (bytes)
#define SA_STRIDE 144        // 64 bf16 (128B) + 16B pad  -> ldmatrix conflict-free
#define SB_STRIDE 272        // 128 bf16 (256B) + 16B pad
#define OFF_AH 0
#define OFF_AL 18432         // 128 * 144
#define OFF_BH 36864
#define OFF_BL 54272         // + 64 * 272
#define SMEM_MM 71680        // total

// ---------------- scratch (no allocs allowed) ----------------
__device__ float g_dinv[N_NODES];
__device__ __align__(16) float g_xp[(size_t)N_NODES * D_IN];
__device__ __align__(16) float g_y[(size_t)N_NODES * D_IN];
__device__ __align__(16) float g_z[(size_t)N_NODES * D_HID];
__device__ __align__(16) float g_lin[(size_t)N_NODES * D_HID];
__device__ float g_sum[D_HID];
__device__ float g_sumsq[D_HID];
// CSR scratch
__device__ int g_deg[N_NODES];
__device__ int g_rowptr[N_NODES + 1];
__device__ int g_cursor[N_NODES];
__device__ int g_csrc[N_EDGES];
__device__ int g_btot[N_CHUNKS];
__device__ int g_boff[N_CHUNKS];
// bf16 hi/lo weights, SAME [k][n] orientation as inputs
__device__ __align__(16) unsigned short gWgHi[65536], gWgLo[65536];   // W_gate 256x256
__device__ __align__(16) unsigned short gWcHi[16384], gWcLo[16384];   // W_gcn 64x256
__device__ __align__(16) unsigned short gWlHi[16384], gWlLo[16384];   // W_lin 64x256

// ---------------- mma / ldmatrix helpers (baseline PTX, sm_80+) ----------------
__device__ __forceinline__ uint32_t smem_u32(const void* p) {
    uint32_t a;
    asm("{ .reg .u64 t; cvta.to.shared.u64 t, %1; cvt.u32.u64 %0, t; }"
        : "=r"(a) : "l"(p));
    return a;
}
__device__ __forceinline__ void ldsm_x4(uint32_t addr, uint32_t* r) {
    asm volatile("ldmatrix.sync.aligned.m8n8.x4.shared.b16 {%0,%1,%2,%3}, [%4];"
                 : "=r"(r[0]), "=r"(r[1]), "=r"(r[2]), "=r"(r[3]) : "r"(addr));
}
__device__ __forceinline__ void ldsm_x4t(uint32_t addr, uint32_t* r) {
    asm volatile("ldmatrix.sync.aligned.m8n8.x4.trans.shared.b16 {%0,%1,%2,%3}, [%4];"
                 : "=r"(r[0]), "=r"(r[1]), "=r"(r[2]), "=r"(r[3]) : "r"(addr));
}
__device__ __forceinline__ void mma_bf16(float* d, const uint32_t* a,
                                         uint32_t b0, uint32_t b1) {
    asm volatile("mma.sync.aligned.m16n8k16.row.col.f32.bf16.bf16.f32 "
                 "{%0,%1,%2,%3}, {%4,%5,%6,%7}, {%8,%9}, {%0,%1,%2,%3};"
                 : "+f"(d[0]), "+f"(d[1]), "+f"(d[2]), "+f"(d[3])
                 : "r"(a[0]), "r"(a[1]), "r"(a[2]), "r"(a[3]), "r"(b0), "r"(b1));
}
__device__ __forceinline__ unsigned short bfh(float a) {
    __nv_bfloat16 h = __float2bfloat16_rn(a);
    return reinterpret_cast<unsigned short&>(h);
}
__device__ __forceinline__ float bf2f(unsigned short u) {
    __nv_bfloat16 h = reinterpret_cast<__nv_bfloat16&>(u);
    return __bfloat162float(h);
}
// convert float4 -> hi uint2 (4 bf16) + lo uint2; memory order: low half = lower k
__device__ __forceinline__ void cvt4(float4 v, uint2& hi, uint2& lo) {
    unsigned short h0 = bfh(v.x), h1 = bfh(v.y), h2 = bfh(v.z), h3 = bfh(v.w);
    hi.x = ((uint32_t)h1 << 16) | h0;
    hi.y = ((uint32_t)h3 << 16) | h2;
    unsigned short l0 = bfh(v.x - bf2f(h0)), l1 = bfh(v.y - bf2f(h1));
    unsigned short l2 = bfh(v.z - bf2f(h2)), l3 = bfh(v.w - bf2f(h3));
    lo.x = ((uint32_t)l1 << 16) | l0;
    lo.y = ((uint32_t)l3 << 16) | l2;
}

// ---------------- K0: zero degree + BN stats ----------------
__global__ void k_init() {
    int i = blockIdx.x * blockDim.x + threadIdx.x;
    if (i < N_NODES) g_deg[i] = 0;
    if (i < D_HID) { g_sum[i] = 0.0f; g_sumsq[i] = 0.0f; }
}

// ---------------- K0b: weights -> bf16 hi/lo (same layout, coalesced) ----------------
__global__ void k_wconv(const float* __restrict__ Wg, const float* __restrict__ Wc,
                        const float* __restrict__ Wl) {
    int i = blockIdx.x * blockDim.x + threadIdx.x;   // 98304 total
    float v;
    unsigned short* dh;
    unsigned short* dl;
    int idx;
    if (i < 65536)      { v = Wg[i]; dh = gWgHi; dl = gWgLo; idx = i; }
    else if (i < 81920) { idx = i - 65536; v = Wc[idx]; dh = gWcHi; dl = gWcLo; }
    else if (i < 98304) { idx = i - 81920; v = Wl[idx]; dh = gWlHi; dl = gWlLo; }
    else return;
    unsigned short h = bfh(v);
    dh[idx] = h;
    dl[idx] = bfh(v - bf2f(h));
}

// ---------------- K1: degree histogram over dst ----------------
__global__ void k_degree(const int* __restrict__ ei) {
    int e = blockIdx.x * blockDim.x + threadIdx.x;
    if (e < N_EDGES) atomicAdd(&g_deg[ei[N_EDGES + e]], 1);
}

// ---------------- K2a: per-1024-chunk exclusive scan + chunk totals ----------------
__global__ void __launch_bounds__(1024) k_scan1() {
    __shared__ int warpsums[32];
    int t = threadIdx.x, lane = t & 31, w = t >> 5;
    int i = blockIdx.x * 1024 + t;
    int v = (i < N_NODES) ? g_deg[i] : 0;
    int x = v;
#pragma unroll
    for (int off = 1; off < 32; off <<= 1) {
        int y = __shfl_up_sync(0xffffffffu, x, off);
        if (lane >= off) x += y;
    }
    if (lane == 31) warpsums[w] = x;
    __syncthreads();
    if (w == 0) {
        int s = warpsums[lane];
#pragma unroll
        for (int off = 1; off < 32; off <<= 1) {
            int y = __shfl_up_sync(0xffffffffu, s, off);
            if (lane >= off) s += y;
        }
        warpsums[lane] = s;
    }
    __syncthreads();
    int excl = ((w > 0) ? warpsums[w - 1] : 0) + x - v;
    if (i < N_NODES) g_rowptr[i] = excl;
    if (t == 0) g_btot[blockIdx.x] = warpsums[31];
}

// ---------------- K2b: scan chunk totals ----------------
__global__ void k_scan2() {
    __shared__ int w0tot;
    int t = threadIdx.x, lane = t & 31, w = t >> 5;
    int v = (t < N_CHUNKS) ? g_btot[t] : 0;
    int x = v;
#pragma unroll
    for (int off = 1; off < 32; off <<= 1) {
        int y = __shfl_up_sync(0xffffffffu, x, off);
        if (lane >= off) x += y;
    }
    if (w == 0 && lane == 31) w0tot = x;
    __syncthreads();
    int excl = x - v + (w ? w0tot : 0);
    if (t < N_CHUNKS) g_boff[t] = excl;
    if (t == N_CHUNKS - 1) g_rowptr[N_NODES] = excl + v;
}

// ---------------- K2c: apply chunk offsets; cursor; dinv ----------------
__global__ void k_scan3() {
    int i = blockIdx.x * blockDim.x + threadIdx.x;
    if (i < N_NODES) {
        int rp = g_rowptr[i] + g_boff[i >> 10];
        g_rowptr[i] = rp;
        g_cursor[i] = rp;
        g_dinv[i] = rsqrtf((float)(g_deg[i] + 1));
    }
}

// ---------------- K3: CSR fill ----------------
__global__ void k_fill(const int* __restrict__ ei) {
    int e = blockIdx.x * blockDim.x + threadIdx.x;
    if (e < N_EDGES) {
        int s = ei[e];
        int d = ei[N_EDGES + e];
        int pos = atomicAdd(&g_cursor[d], 1);
        g_csrc[pos] = s;
    }
}

// ---------------- K3b: xs' = xs * dinv[row] ----------------
__global__ void k_xscale(const float* __restrict__ xs) {
    int i = blockIdx.x * blockDim.x + threadIdx.x;
    if (i < N_NODES * D_IN / 4) {
        float di = g_dinv[i >> 4];
        float4 v = ((const float4*)xs)[i];
        v.x *= di; v.y *= di; v.z *= di; v.w *= di;
        ((float4*)g_xp)[i] = v;
    }
}

// ---------------- K4: CSR gather in D_IN space ----------------
__global__ void __launch_bounds__(256) k_gather_x() {
    int t = threadIdx.x;
    int n = blockIdx.x * 16 + (t >> 4);
    int c = t & 15;
    int g0 = t & ~15;
    const float4* X = (const float4*)g_xp;

    int r_s = 0, e_s = 0;
    float di_s = 0.0f;
    if (c == 0) {
        r_s = g_rowptr[n];
        e_s = g_rowptr[n + 1];
        di_s = g_dinv[n];
    }
    int r  = __shfl_sync(0xffffffffu, r_s, g0 & 31);
    int e  = __shfl_sync(0xffffffffu, e_s, g0 & 31);
    float di = __shfl_sync(0xffffffffu, di_s, g0 & 31);

    float4 acc = X[(size_t)n * 16 + c];
    for (; r + 4 <= e; r += 4) {
        int i0 = __ldg(&g_csrc[r]);
        int i1 = __ldg(&g_csrc[r + 1]);
        int i2 = __ldg(&g_csrc[r + 2]);
        int i3 = __ldg(&g_csrc[r + 3]);
        float4 a0 = X[(size_t)i0 * 16 + c];
        float4 a1 = X[(size_t)i1 * 16 + c];
        float4 a2 = X[(size_t)i2 * 16 + c];
        float4 a3 = X[(size_t)i3 * 16 + c];
        acc.x += (a0.x + a1.x) + (a2.x + a3.x);
        acc.y += (a0.y + a1.y) + (a2.y + a3.y);
        acc.z += (a0.z + a1.z) + (a2.z + a3.z);
        acc.w += (a0.w + a1.w) + (a2.w + a3.w);
    }
    for (; r < e; r++) {
        float4 a0 = X[(size_t)__ldg(&g_csrc[r]) * 16 + c];
        acc.x += a0.x; acc.y += a0.y; acc.z += a0.z; acc.w += a0.w;
    }
    acc.x *= di; acc.y *= di; acc.z *= di; acc.w *= di;
    ((float4*)g_y)[(size_t)n * 16 + c] = acc;
}

// ======= shared device routines for the mma kernels =======

// load + bf16-split a 128x64 fp32 activation tile into smem A (hi/lo), zero OOB rows
__device__ __forceinline__ void load_A_tile(char* smem, const float* __restrict__ src,
                                            int n0, int row_stride_f, int kofs, int tid) {
#pragma unroll
    for (int i = 0; i < 8; i++) {
        int j = tid + 256 * i;          // 0..2047
        int m = j >> 4, k4 = j & 15;
        int node = n0 + m;
        float4 v = make_float4(0.f, 0.f, 0.f, 0.f);
        if (node < N_NODES)
            v = *(const float4*)(src + (size_t)node * row_stride_f + kofs + k4 * 4);
        uint2 hi, lo;
        cvt4(v, hi, lo);
        *(uint2*)(smem + OFF_AH + m * SA_STRIDE + k4 * 8) = hi;
        *(uint2*)(smem + OFF_AL + m * SA_STRIDE + k4 * 8) = lo;
    }
}

// copy a 64(k) x 128(n) bf16 weight slice into smem B (hi/lo)
__device__ __forceinline__ void load_B_tile(char* smem, const unsigned short* __restrict__ Whi,
                                            const unsigned short* __restrict__ Wlo,
                                            int krow0, int row_len, int ncol0, int tid) {
#pragma unroll
    for (int i = 0; i < 4; i++) {
        int j = tid + 256 * i;          // 0..1023
        int r = j >> 4, off = j & 15;   // k row, uint4 col
        size_t s = ((size_t)(krow0 + r) * row_len + ncol0) / 8 + off;
        *(uint4*)(smem + OFF_BH + r * SB_STRIDE + off * 16) = ((const uint4*)Whi)[s];
        *(uint4*)(smem + OFF_BL + r * SB_STRIDE + off * 16) = ((const uint4*)Wlo)[s];
    }
}

// one K=64 tile of 3-split mma into acc[2][8][4]
__device__ __forceinline__ void mma_tile(uint32_t su, float acc[2][8][4],
                                         int m0w, int n0w, int lane) {
    uint32_t a_row = lane & 15;
    uint32_t a_koff = (lane >> 4) << 3;
    uint32_t b_k = (lane & 7) + ((lane & 16) >> 1);
    uint32_t b_n = lane & 8;
#pragma unroll
    for (int ks = 0; ks < 4; ks++) {
        int k0 = ks * 16;
        uint32_t aH[2][4], aL[2][4];
#pragma unroll
        for (int mf = 0; mf < 2; mf++) {
            uint32_t ra = su + OFF_AH + (m0w + mf * 16 + a_row) * SA_STRIDE + (k0 + a_koff) * 2;
            ldsm_x4(ra, aH[mf]);
            ldsm_x4(ra + (OFF_AL - OFF_AH), aL[mf]);
        }
#pragma unroll
        for (int nf2 = 0; nf2 < 4; nf2++) {
            int n0f = n0w + nf2 * 16;
            uint32_t rb = su + OFF_BH + (k0 + b_k) * SB_STRIDE + (n0f + b_n) * 2;
            uint32_t bH[4], bL[4];
            ldsm_x4t(rb, bH);
            ldsm_x4t(rb + (OFF_BL - OFF_BH), bL);
#pragma unroll
            for (int mf = 0; mf < 2; mf++) {
                float* d0 = acc[mf][2 * nf2 + 0];
                float* d1 = acc[mf][2 * nf2 + 1];
                mma_bf16(d0, aH[mf], bH[0], bH[2]);
                mma_bf16(d1, aH[mf], bH[1], bH[3]);
                mma_bf16(d0, aH[mf], bL[0], bL[2]);
                mma_bf16(d1, aH[mf], bL[1], bL[3]);
                mma_bf16(d0, aL[mf], bH[0], bH[2]);
                mma_bf16(d1, aL[mf], bH[1], bH[3]);
            }
        }
    }
}

// ---------------- K5: mma GCN + LIN: z = tanh(y@Wc + b), g_lin = xs@Wl + b ----------------
__global__ void __launch_bounds__(256) k_gcn_mma(const float* __restrict__ xs,
                                                 const float* __restrict__ b_gcn,
                                                 const float* __restrict__ b_lin) {
    extern __shared__ __align__(16) char smem[];
    uint32_t su = smem_u32(smem);
    int tid = threadIdx.x, lane = tid & 31, wid = tid >> 5;
    int n0 = blockIdx.x * 128;
    int ntile = blockIdx.y;
    int m0w = (wid >> 1) * 32, n0w = (wid & 1) * 64;
    int a_r = lane >> 2, a_c = (lane & 3) << 1;

    float acc[2][8][4];

    // ---- pass 1: z ----
    load_A_tile(smem, g_y, n0, D_IN, 0, tid);
    load_B_tile(smem, gWcHi, gWcLo, 0, D_HID, ntile * 128, tid);
    __syncthreads();
#pragma unroll
    for (int mf = 0; mf < 2; mf++)
#pragma unroll
        for (int nf = 0; nf < 8; nf++)
#pragma unroll
            for (int q = 0; q < 4; q++) acc[mf][nf][q] = 0.0f;
    mma_tile(su, acc, m0w, n0w, lane);
#pragma unroll
    for (int mf = 0; mf < 2; mf++) {
#pragma unroll
        for (int nf = 0; nf < 8; nf++) {
            int row = m0w + mf * 16 + a_r;
            int col = ntile * 128 + n0w + nf * 8 + a_c;
            float b0 = __ldg(b_gcn + col), b1 = __ldg(b_gcn + col + 1);
            int node0 = n0 + row, node1 = node0 + 8;
            if (node0 < N_NODES) {
                float2 o = make_float2(tanhf(acc[mf][nf][0] + b0),
                                       tanhf(acc[mf][nf][1] + b1));
                *(float2*)(g_z + (size_t)node0 * D_HID + col) = o;
            }
            if (node1 < N_NODES) {
                float2 o = make_float2(tanhf(acc[mf][nf][2] + b0),
                                       tanhf(acc[mf][nf][3] + b1));
                *(float2*)(g_z + (size_t)node1 * D_HID + col) = o;
            }
        }
    }
    __syncthreads();

    // ---- pass 2: g_lin ----
    load_A_tile(smem, xs, n0, D_IN, 0, tid);
    load_B_tile(smem, gWlHi, gWlLo, 0, D_HID, ntile * 128, tid);
    __syncthreads();
#pragma unroll
    for (int mf = 0; mf < 2; mf++)
#pragma unroll
        for (int nf = 0; nf < 8; nf++)
#pragma unroll
            for (int q = 0; q < 4; q++) acc[mf][nf][q] = 0.0f;
    mma_tile(su, acc, m0w, n0w, lane);
#pragma unroll
    for (int mf = 0; mf < 2; mf++) {
#pragma unroll
        for (int nf = 0; nf < 8; nf++) {
            int row = m0w + mf * 16 + a_r;
            int col = ntile * 128 + n0w + nf * 8 + a_c;
            float b0 = __ldg(b_lin + col), b1 = __ldg(b_lin + col + 1);
            int node0 = n0 + row, node1 = node0 + 8;
            if (node0 < N_NODES) {
                float2 o = make_float2(acc[mf][nf][0] + b0, acc[mf][nf][1] + b1);
                *(float2*)(g_lin + (size_t)node0 * D_HID + col) = o;
            }
            if (node1 < N_NODES) {
                float2 o = make_float2(acc[mf][nf][2] + b0, acc[mf][nf][3] + b1);
                *(float2*)(g_lin + (size_t)node1 * D_HID + col) = o;
            }
        }
    }
}

// ---------------- K6: mma gate GEMM (K=256) + fused epilogue ----------------
__global__ void __launch_bounds__(256) k_gate_mma(const float* __restrict__ b_gate,
                                                  float* __restrict__ out) {
    extern __shared__ __align__(16) char smem[];
    uint32_t su = smem_u32(smem);
    int tid = threadIdx.x, lane = tid & 31, wid = tid >> 5;
    int n0 = blockIdx.x * 128;
    int ntile = blockIdx.y;
    int m0w = (wid >> 1) * 32, n0w = (wid & 1) * 64;
    int a_r = lane >> 2, a_c = (lane & 3) << 1;

    float acc[2][8][4];
#pragma unroll
    for (int mf = 0; mf < 2; mf++)
#pragma unroll
        for (int nf = 0; nf < 8; nf++)
#pragma unroll
            for (int q = 0; q < 4; q++) acc[mf][nf][q] = 0.0f;

    for (int kt = 0; kt < 4; kt++) {
        if (kt) __syncthreads();
        load_A_tile(smem, g_z, n0, D_HID, kt * 64, tid);
        load_B_tile(smem, gWgHi, gWgLo, kt * 64, D_HID, ntile * 128, tid);
        __syncthreads();
        mma_tile(su, acc, m0w, n0w, lane);
    }

#pragma unroll
    for (int mf = 0; mf < 2; mf++) {
#pragma unroll
        for (int nf = 0; nf < 8; nf++) {
            int row = m0w + mf * 16 + a_r;
            int col = ntile * 128 + n0w + nf * 8 + a_c;
            float b0 = __ldg(b_gate + col), b1 = __ldg(b_gate + col + 1);
            int node0 = n0 + row, node1 = node0 + 8;
            if (node0 < N_NODES) {
                float2 l = *(const float2*)(g_lin + (size_t)node0 * D_HID + col);
                float2 z = *(const float2*)(g_z + (size_t)node0 * D_HID + col);
                float gg0 = 1.0f / (1.0f + expf(-(acc[mf][nf][0] + b0)));
                float gg1 = 1.0f / (1.0f + expf(-(acc[mf][nf][1] + b1)));
                float2 o;
                o.x = fmaxf((1.0f - gg0) * l.x + gg0 * z.x, 0.0f);
                o.y = fmaxf((1.0f - gg1) * l.y + gg1 * z.y, 0.0f);
                *(float2*)(out + (size_t)node0 * D_HID + col) = o;
            }
            if (node1 < N_NODES) {
                float2 l = *(const float2*)(g_lin + (size_t)node1 * D_HID + col);
                float2 z = *(const float2*)(g_z + (size_t)node1 * D_HID + col);
                float gg0 = 1.0f / (1.0f + expf(-(acc[mf][nf][2] + b0)));
                float gg1 = 1.0f / (1.0f + expf(-(acc[mf][nf][3] + b1)));
                float2 o;
                o.x = fmaxf((1.0f - gg0) * l.x + gg0 * z.x, 0.0f);
                o.y = fmaxf((1.0f - gg1) * l.y + gg1 * z.y, 0.0f);
                *(float2*)(out + (size_t)node1 * D_HID + col) = o;
            }
        }
    }
}

// ---------------- K7: BN partial stats ----------------
__global__ void __launch_bounds__(D_HID) k_stats(const float* __restrict__ out) {
    int j = threadIdx.x;
    int rows_per_block = (N_NODES + gridDim.x - 1) / gridDim.x;
    int r0 = blockIdx.x * rows_per_block;
    int r1 = r0 + rows_per_block;
    if (r1 > N_NODES) r1 = N_NODES;
    float s = 0.0f, q = 0.0f;
    for (int r = r0; r < r1; r++) {
        float v = out[(size_t)r * D_HID + j];
        s += v;
        q += v * v;
    }
    if (r1 > r0) {
        atomicAdd(&g_sum[j], s);
        atomicAdd(&g_sumsq[j], q);
    }
}

// ---------------- K8: BN normalize in place (float4) ----------------
__global__ void k_bn(float* __restrict__ out,
                     const float* __restrict__ gamma,
                     const float* __restrict__ beta) {
    int i = blockIdx.x * blockDim.x + threadIdx.x;
    if (i < N_NODES * D_HID / 4) {
        int c4 = i & 63;
        const float invN = 1.0f / (float)N_NODES;
        float4 s  = ((const float4*)g_sum)[c4];
        float4 q  = ((const float4*)g_sumsq)[c4];
        float4 gm = ((const float4*)gamma)[c4];
        float4 bt = ((const float4*)beta)[c4];
        float4 v  = ((float4*)out)[i];
        float mu, var;
        mu = s.x * invN; var = q.x * invN - mu * mu;
        v.x = (v.x - mu) * rsqrtf(var + BN_EPS) * gm.x + bt.x;
        mu = s.y * invN; var = q.y * invN - mu * mu;
        v.y = (v.y - mu) * rsqrtf(var + BN_EPS) * gm.y + bt.y;
        mu = s.z * invN; var = q.z * invN - mu * mu;
        v.z = (v.z - mu) * rsqrtf(var + BN_EPS) * gm.z + bt.z;
        mu = s.w * invN; var = q.w * invN - mu * mu;
        v.w = (v.w - mu) * rsqrtf(var + BN_EPS) * gm.w + bt.w;
        ((float4*)out)[i] = v;
    }
}

// ---------------- launch ----------------
extern "C" void kernel_launch(void* const* d_in, const int* in_sizes, int n_in,
                              void* d_out, int out_size) {
    const float* xs     = (const float*)d_in[0];
    const int*   ei     = (const int*)d_in[1];   // int32 (JAX x64-disabled)
    const float* W_gcn  = (const float*)d_in[2];
    const float* b_gcn  = (const float*)d_in[3];
    const float* W_lin  = (const float*)d_in[4];
    const float* b_lin  = (const float*)d_in[5];
    const float* W_gate = (const float*)d_in[6];
    const float* b_gate = (const float*)d_in[7];
    const float* gamma  = (const float*)d_in[8];
    const float* beta   = (const float*)d_in[9];
    float* out = (float*)d_out;

    cudaFuncSetAttribute(k_gcn_mma, cudaFuncAttributeMaxDynamicSharedMemorySize, SMEM_MM);
    cudaFuncSetAttribute(k_gate_mma, cudaFuncAttributeMaxDynamicSharedMemorySize, SMEM_MM);

    k_init<<<(N_NODES + 255) / 256, 256>>>();
    k_wconv<<<384, 256>>>(W_gate, W_gcn, W_lin);
    k_degree<<<(N_EDGES + 255) / 256, 256>>>(ei);
    k_scan1<<<N_CHUNKS, 1024>>>();
    k_scan2<<<1, 64>>>();
    k_scan3<<<(N_NODES + 255) / 256, 256>>>();
    k_fill<<<(N_EDGES + 255) / 256, 256>>>(ei);
    k_xscale<<<(N_NODES * D_IN / 4 + 255) / 256, 256>>>(xs);
    k_gather_x<<<N_NODES / 16, 256>>>();
    k_gcn_mma<<<dim3(N_MT, 2), 256, SMEM_MM>>>(xs, b_gcn, b_lin);
    k_gate_mma<<<dim3(N_MT, 2), 256, SMEM_MM>>>(b_gate, out);
    k_stats<<<512, D_HID>>>(out);
    k_bn<<<(N_NODES * D_HID / 4 + 255) / 256, 256>>>(out, gamma, beta);
}